// round 5
// baseline (speedup 1.0000x reference)
#include <cuda_runtime.h>
#include <cuda_bf16.h>
#include <cstdint>

typedef unsigned int u32;
typedef unsigned long long u64;
typedef __nv_bfloat16 bf16;

#define NN 2048
#define NE 6144
#define KDV 128
#define DVO 64
#define DEI 16
#define DEO 16

// =====================  scratch  =====================
__device__ __align__(16) bf16 g_m1A_hi[NN * NE];
__device__ __align__(16) bf16 g_m1A_lo[NN * NE];
__device__ __align__(16) bf16 g_m1B_hi[NN * NE];
__device__ __align__(16) bf16 g_m1B_lo[NN * NE];
__device__ __align__(16) bf16 g_m2A_hi[NE * NN];
__device__ __align__(16) bf16 g_m2A_lo[NE * NN];
__device__ __align__(16) bf16 g_m2B_hi[NE * NN];
__device__ __align__(16) bf16 g_m2B_lo[NE * NN];
__device__ __align__(16) float g_adjAv[NN * NN];
__device__ __align__(16) float g_adjAe[(size_t)NE * NE];
__device__ __align__(16) float g_HW[NN * DVO];
__device__ __align__(16) float g_HeW[NE * DEO];
__device__ __align__(16) float g_HeWs[NE * DEO];
__device__ __align__(16) float g_de[NE];
__device__ __align__(16) float g_dv[NN];
__device__ u32 g_cmaxu[NE];

// =====================  helpers  =====================
__device__ __forceinline__ u32 smem_u32(const void* p) {
    u32 a;
    asm("{ .reg .u64 t; cvta.to.shared.u64 t, %1; cvt.u32.u64 %0, t; }" : "=r"(a) : "l"(p));
    return a;
}

__device__ __forceinline__ void cp16(u32 saddr, const bf16* gptr) {
    asm volatile("cp.async.cg.shared.global [%0], [%1], 16;"
                 :: "r"(saddr), "l"(__cvta_generic_to_global(gptr)) : "memory");
}

#define LDSM4(r, addr)                                                          \
    asm volatile("ldmatrix.sync.aligned.m8n8.x4.shared.b16 {%0,%1,%2,%3}, [%4];" \
                 : "=r"((r)[0]), "=r"((r)[1]), "=r"((r)[2]), "=r"((r)[3]) : "r"(addr))

#define MMA_BF16(d, a, b)                                                        \
    asm volatile("mma.sync.aligned.m16n8k16.row.col.f32.bf16.bf16.f32 "          \
                 "{%0,%1,%2,%3},{%4,%5,%6,%7},{%8,%9},{%0,%1,%2,%3};"            \
                 : "+f"((d)[0]), "+f"((d)[1]), "+f"((d)[2]), "+f"((d)[3])        \
                 : "r"((a)[0]), "r"((a)[1]), "r"((a)[2]), "r"((a)[3]),           \
                   "r"((b)[0]), "r"((b)[1]))

__device__ __forceinline__ void bsplit(float x, bf16& hi, bf16& lo) {
    hi = __float2bfloat16_rn(x);
    lo = __float2bfloat16_rn(x - __bfloat162float(hi));
}
__device__ __forceinline__ u32 pkb2(bf16 a, bf16 b) {
    __nv_bfloat162 h = __halves2bfloat162(a, b);
    return *(u32*)&h;
}
// monotone unsigned key for float max via atomicMax
__device__ __forceinline__ u32 fkey(float f) {
    u32 b = __float_as_uint(f);
    return (b & 0x80000000u) ? ~b : (b | 0x80000000u);
}

// =====================  tiny prologue kernels  =====================
__global__ void k_de(const float* __restrict__ He, const float* __restrict__ pv) {
    int e = blockIdx.x * 256 + threadIdx.x;
    float s = 0.f;
#pragma unroll
    for (int k = 0; k < DEI; k++) s += He[e * DEI + k] * pv[k];
    g_de[e] = s;
}

__global__ void k_hew(const float* __restrict__ He, const float* __restrict__ We) {
    int idx = blockIdx.x * 256 + threadIdx.x;
    int e = idx >> 4, c = idx & 15;
    float s = 0.f;
#pragma unroll
    for (int k = 0; k < DEI; k++) s += He[e * DEI + k] * We[k * DEO + c];
    g_HeW[idx] = s;
}

__global__ void k_hw(const float* __restrict__ Hv, const float* __restrict__ Wv) {
    int idx = blockIdx.x * 256 + threadIdx.x;
    int i = idx >> 6, c = idx & 63;
    float s = 0.f;
#pragma unroll 8
    for (int k = 0; k < KDV; k++) s += Hv[i * KDV + k] * Wv[k * DVO + c];
    g_HW[idx] = s;
}

__global__ void k_cinit() {
    g_cmaxu[blockIdx.x * 256 + threadIdx.x] = 0u;
}

// mult1 prep: B = T (hi/lo), A = T * d_e[col] (hi/lo). [NN][NE] K-major, bf16.
__global__ void k_split1(const float* __restrict__ T) {
    size_t i = (size_t)blockIdx.x * 256 + threadIdx.x;   // float4 index
    float4 t = ((const float4*)T)[i];
    int col = (int)((i * 4) % NE);
    float4 de = *(const float4*)(g_de + col);
    bf16 hx, lx, hy, ly, hz, lz, hw, lw;
    bsplit(t.x, hx, lx); bsplit(t.y, hy, ly); bsplit(t.z, hz, lz); bsplit(t.w, hw, lw);
    ((uint2*)g_m1B_hi)[i] = make_uint2(pkb2(hx, hy), pkb2(hz, hw));
    ((uint2*)g_m1B_lo)[i] = make_uint2(pkb2(lx, ly), pkb2(lz, lw));
    float ax = t.x * de.x, ay = t.y * de.y, az = t.z * de.z, aw = t.w * de.w;
    bsplit(ax, hx, lx); bsplit(ay, hy, ly); bsplit(az, hz, lz); bsplit(aw, hw, lw);
    ((uint2*)g_m1A_hi)[i] = make_uint2(pkb2(hx, hy), pkb2(hz, hw));
    ((uint2*)g_m1A_lo)[i] = make_uint2(pkb2(lx, ly), pkb2(lz, lw));
}

// mult2 prep (transpose): B2[m][k] = T[k][m]; A2[m][k] = T[k][m]*d_v[k]. [NE][NN] bf16.
// Tile: 64 k-rows x 32 m-cols; u32-packed 128B-coalesced stores.
__global__ void k_split2(const float* __restrict__ T) {
    __shared__ float tile[64][33];
    const int m0 = blockIdx.x * 32, k0 = blockIdx.y * 64;
    const int tx = threadIdx.x, ty = threadIdx.y;     // (32, 8)
#pragma unroll
    for (int j = 0; j < 8; j++) {
        int r = ty + j * 8;
        tile[r][tx] = T[(size_t)(k0 + r) * NE + m0 + tx];
    }
    __syncthreads();
    const int lane = tx, w = ty;
    float2 dv = ((const float2*)(g_dv + k0))[lane];
#pragma unroll
    for (int q = 0; q < 4; q++) {
        const int mloc = w + 8 * q;
        const int m = m0 + mloc;
        float v0 = tile[2 * lane][mloc];
        float v1 = tile[2 * lane + 1][mloc];
        const size_t ob = ((size_t)m * NN + k0) >> 1;   // u32 index
        bf16 h0, l0, h1, l1;
        bsplit(v0, h0, l0); bsplit(v1, h1, l1);
        ((u32*)g_m2B_hi)[ob + lane] = pkb2(h0, h1);
        ((u32*)g_m2B_lo)[ob + lane] = pkb2(l0, l1);
        bsplit(v0 * dv.x, h0, l0); bsplit(v1 * dv.y, h1, l1);
        ((u32*)g_m2A_hi)[ob + lane] = pkb2(h0, h1);
        ((u32*)g_m2A_lo)[ob + lane] = pkb2(l0, l1);
    }
}

// =====================  bf16 3-term tensor-core GEMM + fused epilogue  =====================
// CTA tile 128x128, warp 64x32 (2x4 warps), KB=32, 3-stage cp.async, 2 CTAs/SM.
#define KB 32
#define STG_BYTES 32768          // Ahi 8K | Alo 8K | Bhi 8K | Blo 8K
#define NSTAGE 3
#define SMEM_DYN (NSTAGE * STG_BYTES)

__device__ __forceinline__ void stage_load(u32 st0, int s,
        const bf16* __restrict__ Ahi, const bf16* __restrict__ Alo,
        const bf16* __restrict__ Bhi, const bf16* __restrict__ Blo,
        int K, int m0, int n0, int k0, int tid) {
    u32 base = st0 + s * STG_BYTES;
#pragma unroll
    for (int i = 0; i < 2; i++) {
        int id = tid + i * 256;                // 0..511
        int r = id >> 2, c = id & 3;           // 128 rows x 4 16B-chunks
        u32 so = (u32)(r * 64 + ((c ^ (r & 3)) << 4));
        size_t gA = (size_t)(m0 + r) * K + k0 + c * 8;
        size_t gB = (size_t)(n0 + r) * K + k0 + c * 8;
        cp16(base + so, Ahi + gA);
        cp16(base + 8192 + so, Alo + gA);
        cp16(base + 16384 + so, Bhi + gB);
        cp16(base + 24576 + so, Blo + gB);
    }
    asm volatile("cp.async.commit_group;" ::: "memory");
}

__global__ __launch_bounds__(256, 2) void k_mult_mma(int which, const float* __restrict__ adj) {
    extern __shared__ char smem[];
    const bf16 *Ahi, *Alo, *Bhi, *Blo;
    float* C;
    int K, ncols;
    if (which == 0) {
        Ahi = g_m1A_hi; Alo = g_m1A_lo; Bhi = g_m1B_hi; Blo = g_m1B_lo;
        C = g_adjAv; K = NE; ncols = NN;
    } else {
        Ahi = g_m2A_hi; Alo = g_m2A_lo; Bhi = g_m2B_hi; Blo = g_m2B_lo;
        C = g_adjAe; K = NN; ncols = NE;
    }
    const u32 st0 = smem_u32(smem);
    const int tid = threadIdx.x;
    const int lane = tid & 31, wid = tid >> 5;
    const int wm = wid >> 2, wn = wid & 3;          // 2 x 4 warp grid
    const int m0 = blockIdx.y * 128, n0 = blockIdx.x * 128;
    const int nk = K / KB;

    float acc[4][4][4];
#pragma unroll
    for (int i = 0; i < 4; i++)
#pragma unroll
        for (int j = 0; j < 4; j++)
#pragma unroll
            for (int q = 0; q < 4; q++) acc[i][j][q] = 0.f;

    stage_load(st0, 0, Ahi, Alo, Bhi, Blo, K, m0, n0, 0, tid);
    stage_load(st0, 1, Ahi, Alo, Bhi, Blo, K, m0, n0, KB, tid);

    const u32 arow = (u32)(wm * 64 + (lane & 15));
    const u32 brow = (u32)(wn * 32 + (lane & 15));
    const u32 asw = arow & 3, bsw = brow & 3;

    for (int kt = 0; kt < nk; kt++) {
        const int s = kt % NSTAGE;
        if (kt + 1 < nk) asm volatile("cp.async.wait_group 1;" ::: "memory");
        else             asm volatile("cp.async.wait_group 0;" ::: "memory");
        __syncthreads();
        if (kt + 2 < nk)
            stage_load(st0, (kt + 2) % NSTAGE, Ahi, Alo, Bhi, Blo, K, m0, n0, (kt + 2) * KB, tid);

        const u32 base = st0 + s * STG_BYTES;
#pragma unroll
        for (int ks = 0; ks < 2; ks++) {
            const u32 cb = (u32)(ks * 2) + (u32)(lane >> 4);
            u32 Bh[4][2], Bl[4][2];
            const u32 boff = base + 16384 + brow * 64 + ((cb ^ bsw) << 4);
#pragma unroll
            for (int nip = 0; nip < 2; nip++) {
                u32 t[4];
                LDSM4(t, boff + nip * 1024);
                Bh[2 * nip][0] = t[0]; Bh[2 * nip][1] = t[2];
                Bh[2 * nip + 1][0] = t[1]; Bh[2 * nip + 1][1] = t[3];
                LDSM4(t, boff + 8192 + nip * 1024);
                Bl[2 * nip][0] = t[0]; Bl[2 * nip][1] = t[2];
                Bl[2 * nip + 1][0] = t[1]; Bl[2 * nip + 1][1] = t[3];
            }
            const u32 aoff = base + arow * 64 + ((cb ^ asw) << 4);
#pragma unroll
            for (int mi = 0; mi < 4; mi++) {
                u32 ah[4], al[4];
                LDSM4(ah, aoff + mi * 1024);
                LDSM4(al, aoff + 8192 + mi * 1024);
#pragma unroll
                for (int ni = 0; ni < 4; ni++) {
                    MMA_BF16(acc[mi][ni], ah, Bh[ni]);
                    MMA_BF16(acc[mi][ni], ah, Bl[ni]);
                    MMA_BF16(acc[mi][ni], al, Bh[ni]);
                }
            }
        }
        __syncthreads();
    }

    // epilogue: diag -> 1, * adj, store; fused column-max (which==1)
    u32 kmax[4][2];
#pragma unroll
    for (int ni = 0; ni < 4; ni++) { kmax[ni][0] = 0u; kmax[ni][1] = 0u; }

#pragma unroll
    for (int mi = 0; mi < 4; mi++) {
#pragma unroll
        for (int h = 0; h < 2; h++) {
            const int row_g = m0 + wm * 64 + mi * 16 + (lane >> 2) + h * 8;
            const size_t rb = (size_t)row_g * ncols;
#pragma unroll
            for (int ni = 0; ni < 4; ni++) {
                const int col_g = n0 + wn * 32 + ni * 8 + (lane & 3) * 2;
                float v0 = acc[mi][ni][h * 2], v1 = acc[mi][ni][h * 2 + 1];
                if (row_g == col_g) v0 = 1.0f;
                if (row_g == col_g + 1) v1 = 1.0f;
                const float2 a = *(const float2*)(adj + rb + col_g);
                v0 *= a.x; v1 *= a.y;
                *(float2*)(C + rb + col_g) = make_float2(v0, v1);
                if (which == 1) {
                    kmax[ni][0] = max(kmax[ni][0], fkey(v0));
                    kmax[ni][1] = max(kmax[ni][1], fkey(v1));
                }
            }
        }
    }
    if (which == 1) {
        u32* scm = (u32*)smem;
        if (tid < 128) scm[tid] = 0u;
        __syncthreads();
#pragma unroll
        for (int ni = 0; ni < 4; ni++) {
            const int cl = wn * 32 + ni * 8 + (lane & 3) * 2;
            atomicMax(scm + cl, kmax[ni][0]);
            atomicMax(scm + cl + 1, kmax[ni][1]);
        }
        __syncthreads();
        if (tid < 128) atomicMax(g_cmaxu + n0 + tid, scm[tid]);
    }
}

// =====================  Hv_out = adjAv @ HW + b_v  =====================
__global__ __launch_bounds__(256) void k_hv(const float* __restrict__ bv, float* __restrict__ out) {
    __shared__ __align__(16) float As[32 * 32];
    __shared__ __align__(16) float Bs[32 * 64];
    const int tid = threadIdx.x;
    const int tx = tid & 15, ty = tid >> 4;
    const int m0 = blockIdx.x * 32;
    const int arow = tid >> 3, ac4 = (tid & 7) * 4;
    const int brow = tid >> 4, bc4 = (tid & 15) * 4;
    float acc[2][4] = {{0, 0, 0, 0}, {0, 0, 0, 0}};
    for (int k0 = 0; k0 < NN; k0 += 32) {
        float4 fa = *(const float4*)(g_adjAv + (m0 + arow) * NN + k0 + ac4);
        float4 fb0 = *(const float4*)(g_HW + (k0 + brow) * DVO + bc4);
        float4 fb1 = *(const float4*)(g_HW + (k0 + brow + 16) * DVO + bc4);
        __syncthreads();
        As[(ac4 + 0) * 32 + arow] = fa.x; As[(ac4 + 1) * 32 + arow] = fa.y;
        As[(ac4 + 2) * 32 + arow] = fa.z; As[(ac4 + 3) * 32 + arow] = fa.w;
        *(float4*)(Bs + brow * 64 + bc4) = fb0;
        *(float4*)(Bs + (brow + 16) * 64 + bc4) = fb1;
        __syncthreads();
#pragma unroll
        for (int kk = 0; kk < 32; kk++) {
            float a0 = As[kk * 32 + ty * 2];
            float a1 = As[kk * 32 + ty * 2 + 1];
            float4 b = *(const float4*)(Bs + kk * 64 + tx * 4);
            acc[0][0] += a0 * b.x; acc[0][1] += a0 * b.y; acc[0][2] += a0 * b.z; acc[0][3] += a0 * b.w;
            acc[1][0] += a1 * b.x; acc[1][1] += a1 * b.y; acc[1][2] += a1 * b.z; acc[1][3] += a1 * b.w;
        }
    }
    float4 bb = *(const float4*)(bv + tx * 4);
#pragma unroll
    for (int r = 0; r < 2; r++) {
        int row = m0 + ty * 2 + r;
        *(float4*)(out + row * DVO + tx * 4) =
            make_float4(acc[r][0] + bb.x, acc[r][1] + bb.y, acc[r][2] + bb.z, acc[r][3] + bb.w);
    }
}

__global__ void k_dv(const float* __restrict__ Hv, const float* __restrict__ pe) {
    int w = (blockIdx.x * blockDim.x + threadIdx.x) >> 5;
    int lane = threadIdx.x & 31;
    float s = Hv[w * DVO + lane] * pe[lane] + Hv[w * DVO + 32 + lane] * pe[32 + lane];
#pragma unroll
    for (int o = 16; o > 0; o >>= 1) s += __shfl_down_sync(0xffffffffu, s, o);
    if (lane == 0) g_dv[w] = s;
}

// finalize colmax from keys, fold 1/(max+1e-10) into HeW -> HeWs
__global__ void k_cmax2() {
    int col = blockIdx.x * 256 + threadIdx.x;
    u32 k = g_cmaxu[col];
    u32 b = (k & 0x80000000u) ? (k ^ 0x80000000u) : ~k;
    float m = __uint_as_float(b);
    float inv = 1.0f / (m + 1e-10f);
#pragma unroll
    for (int c = 0; c < DEO; c++) g_HeWs[col * DEO + c] = g_HeW[col * DEO + c] * inv;
}

__global__ __launch_bounds__(256) void k_he(const float* __restrict__ be, float* __restrict__ out) {
    __shared__ __align__(16) float As[64 * 64];
    __shared__ __align__(16) float Bs[64 * 16];
    const int tid = threadIdx.x;
    const int c = tid & 15, tr = tid >> 4;
    const int m0 = blockIdx.x * 64;
    const int lc4 = (tid & 15) * 4;
    float acc[4] = {0, 0, 0, 0};
    for (int k0 = 0; k0 < NE; k0 += 64) {
        float4 ra[4]; float rb[4];
#pragma unroll
        for (int q = 0; q < 4; q++) {
            int row = tr + q * 16;
            ra[q] = *(const float4*)(g_adjAe + (size_t)(m0 + row) * NE + k0 + lc4);
            rb[q] = g_HeWs[(k0 + row) * DEO + c];
        }
        __syncthreads();
#pragma unroll
        for (int q = 0; q < 4; q++) {
            int row = tr + q * 16;
            *(float4*)(As + row * 64 + lc4) = ra[q];
            Bs[row * 16 + c] = rb[q];
        }
        __syncthreads();
#pragma unroll 8
        for (int kk = 0; kk < 64; kk++) {
            float b = Bs[kk * 16 + c];
            acc[0] += As[(0 * 16 + tr) * 64 + kk] * b;
            acc[1] += As[(1 * 16 + tr) * 64 + kk] * b;
            acc[2] += As[(2 * 16 + tr) * 64 + kk] * b;
            acc[3] += As[(3 * 16 + tr) * 64 + kk] * b;
        }
    }
    float bc = be[c];
#pragma unroll
    for (int q = 0; q < 4; q++)
        out[(m0 + q * 16 + tr) * DEO + c] = acc[q] + bc;
}

// =====================  launch  =====================
extern "C" void kernel_launch(void* const* d_in, const int* in_sizes, int n_in,
                              void* d_out, int out_size) {
    const float* H_v  = (const float*)d_in[0];
    const float* H_e  = (const float*)d_in[1];
    const float* adjv = (const float*)d_in[2];
    const float* adje = (const float*)d_in[3];
    const float* T    = (const float*)d_in[4];
    const float* W_v  = (const float*)d_in[5];
    const float* b_v  = (const float*)d_in[6];
    const float* p_v  = (const float*)d_in[7];
    const float* W_e  = (const float*)d_in[8];
    const float* b_e  = (const float*)d_in[9];
    const float* p_e  = (const float*)d_in[10];
    float* out = (float*)d_out;
    (void)in_sizes; (void)n_in; (void)out_size;

    cudaFuncSetAttribute(k_mult_mma, cudaFuncAttributeMaxDynamicSharedMemorySize, SMEM_DYN);

    k_de<<<24, 256>>>(H_e, p_v);
    k_hew<<<384, 256>>>(H_e, W_e);
    k_hw<<<512, 256>>>(H_v, W_v);
    k_cinit<<<24, 256>>>();
    k_split1<<<12288, 256>>>(T);
    k_mult_mma<<<dim3(16, 16), 256, SMEM_DYN>>>(0, adjv);   // adjAv
    k_hv<<<64, 256>>>(b_v, out);
    k_dv<<<256, 256>>>(out, p_e);
    k_split2<<<dim3(192, 32), dim3(32, 8)>>>(T);
    k_mult_mma<<<dim3(48, 48), 256, SMEM_DYN>>>(1, adje);   // adjAe + fused colmax
    k_cmax2<<<24, 256>>>();
    k_he<<<96, 256>>>(b_e, out + NN * DVO);
}